// round 1
// baseline (speedup 1.0000x reference)
#include <cuda_runtime.h>
#include <cuda_bf16.h>
#include <cstdint>

// ---------------------------------------------------------------------------
// ChannelMultiHeadAttention: B=1024, C=64, SEQ=14, EMB=64, fp32.
// Per (b,c) pair over x[14,64]:
//   q = xWq^T+bq, k = xWk^T+bk, v = xWv^T+bv
//   energy = q k^T ; energy1 = w_c @ energy ; LayerNorm(14) ; softmax(/8)
//   out = att @ v
// Algebra:
//   energy = x A x^T + (x u1) 1^T + 1 (x u2)^T + c0,  A=Wq^T Wk, u1=Wq^T bk,
//   u2=Wk^T bq, c0=bq.bk
//   out    = (att @ x) Wv^T + bv        (softmax rows sum to 1)
// ---------------------------------------------------------------------------

#define ULL unsigned long long

__device__ float2 g_A[2048];   // interleaved: g_A[d2*64+e] = (A[2d2][e], A[2d2+1][e])
__device__ float2 g_W[2048];   // interleaved: g_W[d2*64+e] = (Wv[e][2d2], Wv[e][2d2+1])
__device__ float  g_u1[64];
__device__ float  g_u2[64];
__device__ float  g_c0[1];

__device__ __forceinline__ ULL fma2(ULL a, ULL b, ULL c) {
    ULL d;
    asm("fma.rn.f32x2 %0, %1, %2, %3;" : "=l"(d) : "l"(a), "l"(b), "l"(c));
    return d;
}
__device__ __forceinline__ float hsum2(ULL u) {
    float lo, hi;
    asm("mov.b64 {%0,%1}, %2;" : "=f"(lo), "=f"(hi) : "l"(u));
    return lo + hi;
}
__device__ __forceinline__ ULL pack2(float x, float y) {
    ULL u;
    asm("mov.b64 %0, {%1,%2};" : "=l"(u) : "f"(x), "f"(y));
    return u;
}

// ---------------------------------------------------------------------------
// Prep kernel: A (interleaved), Wv^T (interleaved), u1, u2, c0
// ---------------------------------------------------------------------------
__global__ void prep_kernel(const float* __restrict__ Wq, const float* __restrict__ bq,
                            const float* __restrict__ Wk, const float* __restrict__ bk,
                            const float* __restrict__ Wv) {
    __shared__ float sWq[4096], sWk[4096];
    int t = threadIdx.x;
    for (int i = t; i < 4096; i += 256) { sWq[i] = Wq[i]; sWk[i] = Wk[i]; }
    __syncthreads();

    for (int idx = t; idx < 2048; idx += 256) {
        int d2 = idx >> 6, e = idx & 63;
        float a0 = 0.f, a1 = 0.f;
        #pragma unroll 8
        for (int f = 0; f < 64; f++) {
            float wk = sWk[f * 64 + e];
            a0 += sWq[f * 64 + 2 * d2] * wk;
            a1 += sWq[f * 64 + 2 * d2 + 1] * wk;
        }
        g_A[idx] = make_float2(a0, a1);
        g_W[idx] = make_float2(Wv[e * 64 + 2 * d2], Wv[e * 64 + 2 * d2 + 1]);
    }
    if (t < 64) {
        float s1 = 0.f, s2 = 0.f;
        for (int f = 0; f < 64; f++) {
            s1 += sWq[f * 64 + t] * bk[f];
            s2 += sWk[f * 64 + t] * bq[f];
        }
        g_u1[t] = s1; g_u2[t] = s2;
    }
    if (t == 0) {
        float c = 0.f;
        for (int f = 0; f < 64; f++) c += bq[f] * bk[f];
        g_c0[0] = c;
    }
}

// ---------------------------------------------------------------------------
// Main fused kernel: 1 warp = 1 (b,c) pair, 8 pairs per CTA.
// ---------------------------------------------------------------------------
// Row stride for x/z tiles in shared: 33 ULLs (66 floats) -> conflict-free
// lane-varying row reads in the energy phase.
static const int SMEM_BYTES = (2048 + 2048 + 8 * 14 * 33 + 8 * 14 * 33) * 8   // sA,sW,sx,sy
                            + (8 * 14 * 15 + 64 * 3 + 196 + 14 + 14 + 8 * 14) * 4;

__global__ __launch_bounds__(256, 2)
void attn_kernel(const float* __restrict__ x, const float* __restrict__ wc,
                 const float* __restrict__ lng, const float* __restrict__ lnb,
                 const float* __restrict__ bv, float* __restrict__ out) {
    extern __shared__ ULL sm[];
    ULL* sA = sm;                      // 2048
    ULL* sW = sA + 2048;               // 2048
    ULL* sx = sW + 2048;               // 8 * 462
    ULL* sy = sx + 8 * 462;            // 8 * 462  (y, later z)
    float* se   = (float*)(sy + 8 * 462);  // 8 * 14 * 15
    float* su1  = se + 8 * 210;
    float* su2  = su1 + 64;
    float* sbv  = su2 + 64;
    float* swcs = sbv + 64;            // 196
    float* slg  = swcs + 196;          // 14
    float* slb  = slg + 14;            // 14
    float* sxu2 = slb + 14;            // 8 * 14

    const int t = threadIdx.x, wid = t >> 5, l = t & 31;

    // stage constants
    const ULL* gA = (const ULL*)g_A;
    const ULL* gW = (const ULL*)g_W;
    for (int i = t; i < 2048; i += 256) { sA[i] = gA[i]; sW[i] = gW[i]; }
    if (t < 64) { su1[t] = g_u1[t]; su2[t] = g_u2[t]; sbv[t] = bv[t]; }
    for (int i = t; i < 196; i += 256) swcs[i] = wc[i];
    if (t < 14) { slg[t] = lng[t]; slb[t] = lnb[t]; }
    __syncthreads();
    const float c0 = g_c0[0];

    const size_t pair = (size_t)blockIdx.x * 8 + wid;
    const float* xg = x + pair * 896;
    ULL* xrow = sx + wid * 462;   // 14 rows x 33 ULL
    ULL* yrow = sy + wid * 462;
    float* sep   = se + wid * 210;  // 14 x 15
    float* sxu2p = sxu2 + wid * 14;

    // ---- load x tile (coalesced 16B) into padded shared ----
    const ulonglong2* xg2 = (const ulonglong2*)xg;
    for (int k = l; k < 224; k += 32) {
        ulonglong2 v = xg2[k];
        int i = k >> 4;           // row (16 float4 per row)
        int c4 = k & 15;
        xrow[i * 33 + c4 * 2]     = v.x;
        xrow[i * 33 + c4 * 2 + 1] = v.y;
    }
    __syncwarp();

    // ---- xu1[i], xu2[i] (bias rank-1 terms), lanes 0..13 ----
    float xu1 = 0.f;
    if (l < 14) {
        const float* xr = (const float*)(xrow + l * 33);
        float a = 0.f, b = 0.f;
        #pragma unroll 8
        for (int d = 0; d < 64; d++) { a += xr[d] * su1[d]; b += xr[d] * su2[d]; }
        xu1 = a;
        sxu2p[l] = b;
    }
    __syncwarp();

    // ---- phase Y: y = x @ A  (lane owns cols l and l+32) ----
    ULL acc0[14], acc1[14];
    #pragma unroll
    for (int i = 0; i < 14; i++) { acc0[i] = 0ULL; acc1[i] = 0ULL; }
    #pragma unroll 2
    for (int d2 = 0; d2 < 32; d2++) {
        ULL a0 = sA[d2 * 64 + l];
        ULL a1 = sA[d2 * 64 + l + 32];
        #pragma unroll
        for (int i = 0; i < 14; i++) {
            ULL xv = xrow[i * 33 + d2];
            acc0[i] = fma2(xv, a0, acc0[i]);
            acc1[i] = fma2(xv, a1, acc1[i]);
        }
    }
    #pragma unroll
    for (int i = 0; i < 14; i++) {
        ((float*)(yrow + i * 33))[l]      = hsum2(acc0[i]);
        ((float*)(yrow + i * 33))[l + 32] = hsum2(acc1[i]);
    }
    __syncwarp();

    // ---- energy[i][j] = y_i . x_j + xu1[i] + xu2[j] + c0  (lanes 0..13) ----
    if (l < 14) {
        const ULL* yr = yrow + l * 33;
        #pragma unroll
        for (int j = 0; j < 14; j++) {
            const ULL* xj = xrow + j * 33;
            ULL aA = 0ULL, aB = 0ULL;
            #pragma unroll
            for (int d2 = 0; d2 < 32; d2 += 2) {
                aA = fma2(yr[d2],     xj[d2],     aA);
                aB = fma2(yr[d2 + 1], xj[d2 + 1], aB);
            }
            sep[l * 15 + j] = hsum2(aA) + hsum2(aB) + xu1 + sxu2p[j] + c0;
        }
    }
    __syncwarp();

    // ---- mix (w_c @ energy) + LayerNorm + softmax (lane a = l < 14) ----
    float att[14];
    if (l < 14) {
        float e1[14];
        #pragma unroll
        for (int v = 0; v < 14; v++) e1[v] = 0.f;
        #pragma unroll
        for (int li = 0; li < 14; li++) {
            float w = swcs[l * 14 + li];
            #pragma unroll
            for (int v = 0; v < 14; v++) e1[v] += w * sep[li * 15 + v];
        }
        float mu = 0.f;
        #pragma unroll
        for (int v = 0; v < 14; v++) mu += e1[v];
        mu *= (1.0f / 14.0f);
        float var = 0.f;
        #pragma unroll
        for (int v = 0; v < 14; v++) { float d = e1[v] - mu; var += d * d; }
        var *= (1.0f / 14.0f);
        float rs = rsqrtf(var + 1e-5f);
        float mx = -1e30f;
        #pragma unroll
        for (int v = 0; v < 14; v++) {
            float tv = ((e1[v] - mu) * rs * slg[v] + slb[v]) * 0.125f;  // /sqrt(64)
            e1[v] = tv;
            mx = fmaxf(mx, tv);
        }
        float s = 0.f;
        #pragma unroll
        for (int v = 0; v < 14; v++) { float ev = __expf(e1[v] - mx); att[v] = ev; s += ev; }
        float inv = 1.0f / s;
        #pragma unroll
        for (int v = 0; v < 14; v++) att[v] *= inv;
    }
    __syncwarp();

    // ---- z = att @ x  (lanes 0..13; overwrite y tile) ----
    if (l < 14) {
        ULL ap[14];
        #pragma unroll
        for (int j = 0; j < 14; j++) ap[j] = pack2(att[j], att[j]);
        ULL* zr = yrow + l * 33;
        #pragma unroll 2
        for (int d2 = 0; d2 < 32; d2++) {
            ULL aA = 0ULL, aB = 0ULL;
            #pragma unroll
            for (int j = 0; j < 14; j += 2) {
                aA = fma2(ap[j],     xrow[j * 33 + d2],       aA);
                aB = fma2(ap[j + 1], xrow[(j + 1) * 33 + d2], aB);
            }
            float2 a = *(float2*)&aA, b = *(float2*)&aB;
            zr[d2] = pack2(a.x + b.x, a.y + b.y);
        }
    }
    __syncwarp();

    // ---- out = z @ Wv^T + bv  (lane owns cols l and l+32) ----
    #pragma unroll
    for (int i = 0; i < 14; i++) { acc0[i] = 0ULL; acc1[i] = 0ULL; }
    #pragma unroll 2
    for (int d2 = 0; d2 < 32; d2++) {
        ULL w0 = sW[d2 * 64 + l];
        ULL w1 = sW[d2 * 64 + l + 32];
        #pragma unroll
        for (int i = 0; i < 14; i++) {
            ULL zv = yrow[i * 33 + d2];
            acc0[i] = fma2(zv, w0, acc0[i]);
            acc1[i] = fma2(zv, w1, acc1[i]);
        }
    }
    float b0 = sbv[l], b1 = sbv[l + 32];
    float* og = out + pair * 896;
    #pragma unroll
    for (int i = 0; i < 14; i++) {
        og[i * 64 + l]      = hsum2(acc0[i]) + b0;
        og[i * 64 + l + 32] = hsum2(acc1[i]) + b1;
    }
}

// ---------------------------------------------------------------------------
extern "C" void kernel_launch(void* const* d_in, const int* in_sizes, int n_in,
                              void* d_out, int out_size) {
    const float* x   = (const float*)d_in[0];
    const float* wc  = (const float*)d_in[1];
    const float* Wq  = (const float*)d_in[2];
    const float* bq  = (const float*)d_in[3];
    const float* Wk  = (const float*)d_in[4];
    const float* bk  = (const float*)d_in[5];
    const float* Wv  = (const float*)d_in[6];
    const float* bv  = (const float*)d_in[7];
    const float* lng = (const float*)d_in[8];
    const float* lnb = (const float*)d_in[9];
    float* out = (float*)d_out;

    cudaFuncSetAttribute(attn_kernel, cudaFuncAttributeMaxDynamicSharedMemorySize, SMEM_BYTES);

    prep_kernel<<<1, 256>>>(Wq, bq, Wk, bk, Wv);
    attn_kernel<<<8192, 256, SMEM_BYTES>>>(x, wc, lng, lnb, bv, out);
}

// round 2
// speedup vs baseline: 1.2064x; 1.2064x over previous
#include <cuda_runtime.h>
#include <cuda_bf16.h>
#include <cstdint>

// ---------------------------------------------------------------------------
// ChannelMultiHeadAttention: B=1024, C=64, SEQ=14, EMB=64, fp32.
// Algebra:
//   energy = x A x^T + (x u1) 1^T + 1 (x u2)^T + c0,  A=Wq^T Wk
//   out    = (att @ x) Wv^T + bv        (softmax rows sum to 1)
// R2: LDS.128 tile reads (stride 34 ULL), energy/z split over 28 lanes.
// ---------------------------------------------------------------------------

#define ULL unsigned long long
#define FULLMASK 0xffffffffu
static const int RS = 34;            // row stride in ULL (16B aligned, low-conflict)

__device__ float2 g_A[2048];   // g_A[d2*64+e] = (A[2d2][e], A[2d2+1][e])
__device__ float2 g_W[2048];   // g_W[d2*64+e] = (Wv[e][2d2], Wv[e][2d2+1])
__device__ float  g_u1[64];
__device__ float  g_u2[64];
__device__ float  g_c0[1];

__device__ __forceinline__ ULL fma2(ULL a, ULL b, ULL c) {
    ULL d;
    asm("fma.rn.f32x2 %0, %1, %2, %3;" : "=l"(d) : "l"(a), "l"(b), "l"(c));
    return d;
}
__device__ __forceinline__ float hsum2(ULL u) {
    float lo, hi;
    asm("mov.b64 {%0,%1}, %2;" : "=f"(lo), "=f"(hi) : "l"(u));
    return lo + hi;
}
__device__ __forceinline__ ULL pack2(float x, float y) {
    ULL u;
    asm("mov.b64 %0, {%1,%2};" : "=l"(u) : "f"(x), "f"(y));
    return u;
}
__device__ __forceinline__ float2 unp2(ULL u) {
    float2 f;
    asm("mov.b64 {%0,%1}, %2;" : "=f"(f.x), "=f"(f.y) : "l"(u));
    return f;
}

// ---------------------------------------------------------------------------
__global__ void prep_kernel(const float* __restrict__ Wq, const float* __restrict__ bq,
                            const float* __restrict__ Wk, const float* __restrict__ bk,
                            const float* __restrict__ Wv) {
    __shared__ float sWq[4096], sWk[4096];
    int t = threadIdx.x;
    for (int i = t; i < 4096; i += 256) { sWq[i] = Wq[i]; sWk[i] = Wk[i]; }
    __syncthreads();

    for (int idx = t; idx < 2048; idx += 256) {
        int d2 = idx >> 6, e = idx & 63;
        float a0 = 0.f, a1 = 0.f;
        #pragma unroll 8
        for (int f = 0; f < 64; f++) {
            float wk = sWk[f * 64 + e];
            a0 += sWq[f * 64 + 2 * d2] * wk;
            a1 += sWq[f * 64 + 2 * d2 + 1] * wk;
        }
        g_A[idx] = make_float2(a0, a1);
        g_W[idx] = make_float2(Wv[e * 64 + 2 * d2], Wv[e * 64 + 2 * d2 + 1]);
    }
    if (t < 64) {
        float s1 = 0.f, s2 = 0.f;
        for (int f = 0; f < 64; f++) {
            s1 += sWq[f * 64 + t] * bk[f];
            s2 += sWk[f * 64 + t] * bq[f];
        }
        g_u1[t] = s1; g_u2[t] = s2;
    }
    if (t == 0) {
        float c = 0.f;
        for (int f = 0; f < 64; f++) c += bq[f] * bk[f];
        g_c0[0] = c;
    }
}

// ---------------------------------------------------------------------------
// 1 warp = 1 (b,c) pair, 8 pairs/CTA, 256 threads.
// ---------------------------------------------------------------------------
static const int TILE = 14 * RS;     // 476 ULL per pair tile
static const int SMEM_BYTES = (2048 + 2048 + 8 * TILE + 8 * TILE) * 8
                            + (8 * 210 + 64 * 3 + 196 + 14 + 14 + 8 * 14) * 4;

__global__ __launch_bounds__(256, 2)
void attn_kernel(const float* __restrict__ x, const float* __restrict__ wc,
                 const float* __restrict__ lng, const float* __restrict__ lnb,
                 const float* __restrict__ bv, float* __restrict__ out) {
    extern __shared__ ULL sm[];
    ULL* sA = sm;                      // 2048
    ULL* sW = sA + 2048;               // 2048
    ULL* sx = sW + 2048;               // 8 * 476
    ULL* sy = sx + 8 * TILE;           // 8 * 476 (y, later z)
    float* se   = (float*)(sy + 8 * TILE); // 8 * 14 * 15
    float* su1  = se + 8 * 210;
    float* su2  = su1 + 64;
    float* sbv  = su2 + 64;
    float* swcs = sbv + 64;            // 196
    float* slg  = swcs + 196;          // 14
    float* slb  = slg + 14;            // 14
    float* sxu2 = slb + 14;            // 8 * 14

    const int t = threadIdx.x, wid = t >> 5, l = t & 31;

    // stage constants
    const ULL* gA = (const ULL*)g_A;
    const ULL* gW = (const ULL*)g_W;
    for (int i = t; i < 2048; i += 256) { sA[i] = gA[i]; sW[i] = gW[i]; }
    if (t < 64) { su1[t] = g_u1[t]; su2[t] = g_u2[t]; sbv[t] = bv[t]; }
    for (int i = t; i < 196; i += 256) swcs[i] = wc[i];
    if (t < 14) { slg[t] = lng[t]; slb[t] = lnb[t]; }
    __syncthreads();
    const float c0 = g_c0[0];

    const size_t pair = (size_t)blockIdx.x * 8 + wid;
    const float* xg = x + pair * 896;
    ULL* xrow = sx + wid * TILE;   // 14 rows x 34 ULL
    ULL* yrow = sy + wid * TILE;
    float* sep   = se + wid * 210;  // 14 x 15
    float* sxu2p = sxu2 + wid * 14;

    // ---- load x tile (coalesced 16B) into padded shared ----
    const ulonglong2* xg2 = (const ulonglong2*)xg;
    for (int k = l; k < 224; k += 32) {
        ulonglong2 v = xg2[k];
        int i = k >> 4;           // row (16 float4 per row)
        int c4 = k & 15;
        *(ulonglong2*)&xrow[i * RS + c4 * 2] = v;
    }
    __syncwarp();

    // ---- xu1[i], xu2[i] (bias rank-1 terms), lanes 0..13 ----
    float xu1 = 0.f;
    if (l < 14) {
        const float* xr = (const float*)(xrow + l * RS);
        float a = 0.f, b = 0.f;
        #pragma unroll 8
        for (int d = 0; d < 64; d++) { a += xr[d] * su1[d]; b += xr[d] * su2[d]; }
        xu1 = a;
        sxu2p[l] = b;
    }
    __syncwarp();

    // ---- phase Y: y = x @ A  (lane owns cols l and l+32) ----
    {
        ULL acc0[14], acc1[14];
        #pragma unroll
        for (int i = 0; i < 14; i++) { acc0[i] = 0ULL; acc1[i] = 0ULL; }
        #pragma unroll 4
        for (int d2 = 0; d2 < 32; d2 += 2) {
            ULL a00 = sA[d2 * 64 + l];
            ULL a10 = sA[d2 * 64 + l + 32];
            ULL a01 = sA[(d2 + 1) * 64 + l];
            ULL a11 = sA[(d2 + 1) * 64 + l + 32];
            #pragma unroll
            for (int i = 0; i < 14; i++) {
                ulonglong2 xv = *(const ulonglong2*)&xrow[i * RS + d2];
                acc0[i] = fma2(xv.x, a00, acc0[i]);
                acc1[i] = fma2(xv.x, a10, acc1[i]);
                acc0[i] = fma2(xv.y, a01, acc0[i]);
                acc1[i] = fma2(xv.y, a11, acc1[i]);
            }
        }
        #pragma unroll
        for (int i = 0; i < 14; i++) {
            ((float*)(yrow + i * RS))[l]      = hsum2(acc0[i]);
            ((float*)(yrow + i * RS))[l + 32] = hsum2(acc1[i]);
        }
    }
    __syncwarp();

    // ---- energy[i][j] = y_i . x_j + xu1[i] + xu2[j] + c0 ----
    // 28 active lanes: lanes 0..13 -> (i=l, j=0..6); lanes 16..29 -> (i=l-16, j=7..13)
    {
        float xu1s = __shfl_sync(FULLMASK, xu1, l & 15);
        if ((l & 15) < 14) {
            const int i = l & 15;
            const int jbase = (l >> 4) * 7;
            const ULL* yr = yrow + i * RS;
            #pragma unroll
            for (int jj = 0; jj < 7; jj++) {
                const int j = jbase + jj;
                const ULL* xj = xrow + j * RS;
                ULL aA = 0ULL, aB = 0ULL;
                #pragma unroll
                for (int d4 = 0; d4 < 16; d4++) {
                    ulonglong2 yv = *(const ulonglong2*)&yr[d4 * 2];
                    ulonglong2 xv = *(const ulonglong2*)&xj[d4 * 2];
                    aA = fma2(yv.x, xv.x, aA);
                    aB = fma2(yv.y, xv.y, aB);
                }
                sep[i * 15 + j] = hsum2(aA) + hsum2(aB) + xu1s + sxu2p[j] + c0;
            }
        }
    }
    __syncwarp();

    // ---- mix (w_c @ energy) + LayerNorm + softmax (lanes 0..13) ----
    float att[14];
    #pragma unroll
    for (int v = 0; v < 14; v++) att[v] = 0.f;
    if (l < 14) {
        float e1[14];
        #pragma unroll
        for (int v = 0; v < 14; v++) e1[v] = 0.f;
        #pragma unroll
        for (int li = 0; li < 14; li++) {
            float w = swcs[l * 14 + li];
            #pragma unroll
            for (int v = 0; v < 14; v++) e1[v] += w * sep[li * 15 + v];
        }
        float mu = 0.f;
        #pragma unroll
        for (int v = 0; v < 14; v++) mu += e1[v];
        mu *= (1.0f / 14.0f);
        float var = 0.f;
        #pragma unroll
        for (int v = 0; v < 14; v++) { float d = e1[v] - mu; var += d * d; }
        var *= (1.0f / 14.0f);
        float rs = rsqrtf(var + 1e-5f);
        float mx = -1e30f;
        #pragma unroll
        for (int v = 0; v < 14; v++) {
            float tv = ((e1[v] - mu) * rs * slg[v] + slb[v]) * 0.125f;
            e1[v] = tv;
            mx = fmaxf(mx, tv);
        }
        float s = 0.f;
        #pragma unroll
        for (int v = 0; v < 14; v++) { float ev = __expf(e1[v] - mx); att[v] = ev; s += ev; }
        float inv = 1.0f / s;
        #pragma unroll
        for (int v = 0; v < 14; v++) att[v] *= inv;
    }
    __syncwarp();

    // ---- z = att @ x  (28 lanes: lane handles row i=l&15, d-half l>>4) ----
    {
        ULL ap[14];
        #pragma unroll
        for (int j = 0; j < 14; j++) {
            float av = __shfl_sync(FULLMASK, att[j], l & 15);
            ap[j] = pack2(av, av);
        }
        if ((l & 15) < 14) {
            const int i = l & 15;
            const int dbase = (l >> 4) * 16;
            ULL* zr = yrow + i * RS;
            #pragma unroll
            for (int dd = 0; dd < 16; dd += 2) {
                const int d2 = dbase + dd;
                ULL a0 = 0ULL, a1 = 0ULL;
                #pragma unroll
                for (int j = 0; j < 14; j++) {
                    ulonglong2 xv = *(const ulonglong2*)&xrow[j * RS + d2];
                    a0 = fma2(ap[j], xv.x, a0);
                    a1 = fma2(ap[j], xv.y, a1);
                }
                *(ulonglong2*)&zr[d2] = make_ulonglong2(a0, a1);
            }
        }
    }
    __syncwarp();

    // ---- out = z @ Wv^T + bv  (lane owns cols l and l+32) ----
    {
        ULL acc0[14], acc1[14];
        #pragma unroll
        for (int i = 0; i < 14; i++) { acc0[i] = 0ULL; acc1[i] = 0ULL; }
        #pragma unroll 4
        for (int d2 = 0; d2 < 32; d2 += 2) {
            ULL w00 = sW[d2 * 64 + l];
            ULL w10 = sW[d2 * 64 + l + 32];
            ULL w01 = sW[(d2 + 1) * 64 + l];
            ULL w11 = sW[(d2 + 1) * 64 + l + 32];
            #pragma unroll
            for (int i = 0; i < 14; i++) {
                ulonglong2 zv = *(const ulonglong2*)&yrow[i * RS + d2];
                acc0[i] = fma2(zv.x, w00, acc0[i]);
                acc1[i] = fma2(zv.x, w10, acc1[i]);
                acc0[i] = fma2(zv.y, w01, acc0[i]);
                acc1[i] = fma2(zv.y, w11, acc1[i]);
            }
        }
        float b0 = sbv[l], b1 = sbv[l + 32];
        float* og = out + pair * 896;
        #pragma unroll
        for (int i = 0; i < 14; i++) {
            og[i * 64 + l]      = hsum2(acc0[i]) + b0;
            og[i * 64 + l + 32] = hsum2(acc1[i]) + b1;
        }
    }
}

// ---------------------------------------------------------------------------
extern "C" void kernel_launch(void* const* d_in, const int* in_sizes, int n_in,
                              void* d_out, int out_size) {
    const float* x   = (const float*)d_in[0];
    const float* wc  = (const float*)d_in[1];
    const float* Wq  = (const float*)d_in[2];
    const float* bq  = (const float*)d_in[3];
    const float* Wk  = (const float*)d_in[4];
    const float* bk  = (const float*)d_in[5];
    const float* Wv  = (const float*)d_in[6];
    const float* bv  = (const float*)d_in[7];
    const float* lng = (const float*)d_in[8];
    const float* lnb = (const float*)d_in[9];
    float* out = (float*)d_out;

    cudaFuncSetAttribute(attn_kernel, cudaFuncAttributeMaxDynamicSharedMemorySize, SMEM_BYTES);

    prep_kernel<<<1, 256>>>(Wq, bq, Wk, bk, Wv);
    attn_kernel<<<8192, 256, SMEM_BYTES>>>(x, wc, lng, lnb, bv, out);
}